// round 16
// baseline (speedup 1.0000x reference)
#include <cuda_runtime.h>
#include <cuda_bf16.h>
#include <cstdint>

// Shapes (fixed by the problem)
#define B_   32
#define H_   8
#define C_   64
#define L_   1024
#define HC_  512          // H_*C_
#define K_   6            // int(log(1024)) = 6
#define G_   32           // row-groups per batch in stage-1 reduction
#define RPG_ 16           // rows per group (HC_/G_)
#define TROWS 4           // k_agg rows per block (2 interleaved pairs)

// Scratch (no allocations allowed -> __device__ globals)
__device__ float g_partial[B_ * G_ * L_];   // 4 MB
__device__ float g_meanv[B_ * L_];          // 128 KB
__device__ int   g_idx[K_];
__device__ float g_wts[B_ * K_];
__device__ int   g_cnt[B_ + 1];             // zero-init; self-resetting

// ---------------------------------------------------------------------------
// packed f32x2 helpers (Blackwell FFMA2 — only reachable via PTX)
// ---------------------------------------------------------------------------
__device__ __forceinline__ uint64_t pack2(float x, float y) {
    uint64_t r; asm("mov.b64 %0, {%1, %2};" : "=l"(r) : "f"(x), "f"(y)); return r;
}
__device__ __forceinline__ void unpack2(uint64_t v, float& x, float& y) {
    asm("mov.b64 {%0, %1}, %2;" : "=f"(x), "=f"(y) : "l"(v));
}
__device__ __forceinline__ uint64_t fma2(uint64_t a, uint64_t b, uint64_t c) {
    uint64_t d;
    asm("fma.rn.f32x2 %0, %1, %2, %3;" : "=l"(d) : "l"(a), "l"(b), "l"(c));
    return d;
}

// ---------------------------------------------------------------------------
// Kernel 1: partial reduce of corr over 16-row groups (float4), then a
// last-block-done tail: the 32nd block of batch b combines b's partials into
// g_meanv; the last of those 32 combiners runs top-6 + per-batch softmax.
// All reduction orders are fixed -> deterministic; counters reset themselves
// so the kernel is graph-replay safe. No polling (no deadlock possible).
// grid (B_, G_) = 1024 blocks, 256 threads.
// ---------------------------------------------------------------------------
__global__ __launch_bounds__(256) void k_partial_tail(const float* __restrict__ corr) {
    __shared__ float sm[L_];
    __shared__ float wval[8];
    __shared__ int   widx[8];
    __shared__ int   s_idx[K_];
    __shared__ int   s_flag;

    const int b = blockIdx.x;
    const int g = blockIdx.y;
    const int t = threadIdx.x;

    // ---- phase 1: partial reduce ----
    {
        const float4* __restrict__ base =
            reinterpret_cast<const float4*>(corr) +
            ((size_t)b * HC_ + (size_t)g * RPG_) * (L_ / 4) + t;
        float4 a0 = make_float4(0.f, 0.f, 0.f, 0.f);
        float4 a1 = make_float4(0.f, 0.f, 0.f, 0.f);
#pragma unroll
        for (int r = 0; r < RPG_; r += 2) {
            float4 v0 = base[(size_t)r * (L_ / 4)];
            float4 v1 = base[(size_t)(r + 1) * (L_ / 4)];
            a0.x += v0.x; a0.y += v0.y; a0.z += v0.z; a0.w += v0.w;
            a1.x += v1.x; a1.y += v1.y; a1.z += v1.z; a1.w += v1.w;
        }
        float4 s;
        s.x = a0.x + a1.x; s.y = a0.y + a1.y; s.z = a0.z + a1.z; s.w = a0.w + a1.w;
        reinterpret_cast<float4*>(g_partial)[((size_t)(b * G_ + g)) * (L_ / 4) + t] = s;
    }

    // ---- gate: last block of batch b combines ----
    __threadfence();
    if (t == 0) {
        int old = atomicAdd(&g_cnt[b], 1);
        s_flag = (old == G_ - 1);
    }
    __syncthreads();
    if (!s_flag) return;
    __threadfence();                       // order our reads after the atomic

    // ---- phase 2: combine batch b -> g_meanv[b,:] (fixed g order) ----
#pragma unroll
    for (int j = 0; j < 4; ++j) {
        const int l = t + j * 256;
        float s = 0.f;
#pragma unroll
        for (int gg = 0; gg < G_; ++gg)
            s += g_partial[((size_t)b * G_ + gg) * L_ + l];
        g_meanv[(size_t)b * L_ + l] = s * (1.0f / (float)HC_);
    }
    __syncthreads();

    // ---- gate: last combiner runs topk + softmax ----
    __threadfence();
    if (t == 0) {
        g_cnt[b] = 0;                      // reset for next replay
        int old2 = atomicAdd(&g_cnt[B_], 1);
        s_flag = (old2 == B_ - 1);
    }
    __syncthreads();
    if (!s_flag) return;
    __threadfence();

    // ---- phase 3: batch-sum per column, top-6 (argmax iterate, smaller-index
    // tie-break: same SET as lax.top_k; order irrelevant — the softmax-weighted
    // sum is permutation invariant), then per-batch softmax ----
    const int wid = t >> 5;
    const int lid = t & 31;
#pragma unroll
    for (int j = 0; j < 4; ++j) {
        const int l = t + j * 256;
        float s = 0.f;
#pragma unroll 8
        for (int bb = 0; bb < B_; ++bb) s += g_meanv[(size_t)bb * L_ + l];
        sm[l] = s;
    }
    __syncthreads();

    for (int k = 0; k < K_; ++k) {
        float bv = -3.0e38f; int bi = 0x7fffffff;
#pragma unroll
        for (int j = 0; j < 4; ++j) {
            const int l = t + j * 256;
            const float v = sm[l];
            if (v > bv || (v == bv && l < bi)) { bv = v; bi = l; }
        }
#pragma unroll
        for (int off = 16; off > 0; off >>= 1) {
            float v2 = __shfl_down_sync(0xffffffffu, bv, off);
            int   i2 = __shfl_down_sync(0xffffffffu, bi, off);
            if (v2 > bv || (v2 == bv && i2 < bi)) { bv = v2; bi = i2; }
        }
        if (lid == 0) { wval[wid] = bv; widx[wid] = bi; }
        __syncthreads();
        if (t == 0) {
            float fv = wval[0]; int fi = widx[0];
#pragma unroll
            for (int w = 1; w < 8; ++w) {
                if (wval[w] > fv || (wval[w] == fv && widx[w] < fi)) {
                    fv = wval[w]; fi = widx[w];
                }
            }
            s_idx[k] = fi;
            g_idx[k] = fi;
            sm[fi]   = -3.0e38f;
        }
        __syncthreads();
    }

    if (t < B_) {
        const int bb = t;
        float w[K_];
        float m = -3.0e38f;
#pragma unroll
        for (int k = 0; k < K_; ++k) {
            w[k] = g_meanv[(size_t)bb * L_ + s_idx[k]];
            m = fmaxf(m, w[k]);
        }
        float sum = 0.f;
#pragma unroll
        for (int k = 0; k < K_; ++k) { w[k] = __expf(w[k] - m); sum += w[k]; }
        const float inv = 1.0f / sum;
#pragma unroll
        for (int k = 0; k < K_; ++k) g_wts[bb * K_ + k] = w[k] * inv;
    }
    if (t == 0) g_cnt[B_] = 0;             // reset for next replay
}

// ---------------------------------------------------------------------------
// Kernel 2: delays aggregation, row-pair interleaved + packed FFMA2.
// Rows staged in interleaved pairs (sv[2x]=rowA[x], sv[2x+1]=rowB[x]) so one
// aligned LDS.64 feeds TWO outputs and one fma.rn.f32x2 does both multiplies.
// The smem operand is loaded directly as uint64_t (no float2->pack MOVs) and
// __launch_bounds__(256,7) caps regs so occupancy feeds the L1 pipe.
// ---------------------------------------------------------------------------
__global__ __launch_bounds__(256, 7) void k_agg(const float* __restrict__ values,
                                                float* __restrict__ out) {
    __shared__ float sv[TROWS * L_];        // 16 KB: 2 interleaved pairs
    const int t    = threadIdx.x;
    const int row0 = blockIdx.x * TROWS;    // 4 rows, same batch b
    const int b    = row0 >> 9;             // row0 / (H_*C_)

    // stage 2 pairs interleaved (4 independent LDG.128 per thread)
    const float4* __restrict__ src =
        reinterpret_cast<const float4*>(values + (size_t)row0 * L_);
    float4* sv4 = reinterpret_cast<float4*>(sv);
#pragma unroll
    for (int p = 0; p < TROWS / 2; ++p) {
        float4 a = src[(2 * p)     * 256 + t];   // row A of pair p
        float4 c = src[(2 * p + 1) * 256 + t];   // row B of pair p
        sv4[p * 512 + 2 * t]     = make_float4(a.x, c.x, a.y, c.y);
        sv4[p * 512 + 2 * t + 1] = make_float4(a.z, c.z, a.w, c.w);
    }

    // broadcast weights (packed duplicated) + indices
    uint64_t w2[K_];
    int      ix[K_];
#pragma unroll
    for (int k = 0; k < K_; ++k) {
        const float w = g_wts[b * K_ + k];
        w2[k] = pack2(w, w);
        ix[k] = g_idx[k];
    }

    __syncthreads();

#pragma unroll
    for (int p = 0; p < TROWS / 2; ++p) {
        const uint64_t* sp = reinterpret_cast<const uint64_t*>(sv + p * 2 * L_);
        float* dA = out + (size_t)(row0 + 2 * p) * L_;
        float* dB = dA + L_;
#pragma unroll
        for (int j = 0; j < 4; ++j) {
            const int l = t + j * 256;
            uint64_t acc = 0;                               // (0.0f, 0.0f)
#pragma unroll
            for (int k = 0; k < K_; ++k)
                acc = fma2(sp[(l + ix[k]) & (L_ - 1)], w2[k], acc);  // LDS.64+FFMA2
            float ra, rb;
            unpack2(acc, ra, rb);
            dA[l] = ra;
            dB[l] = rb;
        }
    }
}

// ---------------------------------------------------------------------------
extern "C" void kernel_launch(void* const* d_in, const int* in_sizes, int n_in,
                              void* d_out, int out_size) {
    const float* values = (const float*)d_in[0];
    const float* corr   = (const float*)d_in[1];
    float*       out    = (float*)d_out;

    dim3 g1(B_, G_);
    k_partial_tail<<<g1, 256>>>(corr);
    k_agg<<<(B_ * H_ * C_) / TROWS, 256>>>(values, out);
}

// round 17
// speedup vs baseline: 1.0175x; 1.0175x over previous
#include <cuda_runtime.h>
#include <cuda_bf16.h>
#include <cstdint>

// Shapes (fixed by the problem)
#define B_   32
#define H_   8
#define C_   64
#define L_   1024
#define HC_  512          // H_*C_
#define K_   6            // int(log(1024)) = 6
#define G_   32           // row-groups per batch in stage-1 reduction
#define RPG_ 16           // rows per group (HC_/G_)

// Scratch (no allocations allowed -> __device__ globals)
__device__ float g_partial[B_ * G_ * L_];   // 4 MB
__device__ float g_meanv[B_ * L_];          // 128 KB
__device__ int   g_idx[K_];
__device__ float g_wts[B_ * K_];
__device__ int   g_cnt;                     // zero-init; self-resetting

// ---------------------------------------------------------------------------
// Kernel 1: partial reduce of corr over 16-row groups, float4-vectorized.
// grid (B_, G_) = 1024 blocks, 256 threads. Measured 13.7us / 62% DRAM.
// ---------------------------------------------------------------------------
__global__ __launch_bounds__(256) void k_partial(const float* __restrict__ corr) {
    const int b = blockIdx.x;
    const int g = blockIdx.y;
    const int t = threadIdx.x;
    const float4* __restrict__ base =
        reinterpret_cast<const float4*>(corr) +
        ((size_t)b * HC_ + (size_t)g * RPG_) * (L_ / 4) + t;

    float4 a0 = make_float4(0.f, 0.f, 0.f, 0.f);
    float4 a1 = make_float4(0.f, 0.f, 0.f, 0.f);
#pragma unroll
    for (int r = 0; r < RPG_; r += 2) {
        float4 v0 = base[(size_t)r * (L_ / 4)];
        float4 v1 = base[(size_t)(r + 1) * (L_ / 4)];
        a0.x += v0.x; a0.y += v0.y; a0.z += v0.z; a0.w += v0.w;
        a1.x += v1.x; a1.y += v1.y; a1.z += v1.z; a1.w += v1.w;
    }
    float4 s;
    s.x = a0.x + a1.x; s.y = a0.y + a1.y; s.z = a0.z + a1.z; s.w = a0.w + a1.w;
    reinterpret_cast<float4*>(g_partial)[((size_t)(b * G_ + g)) * (L_ / 4) + t] = s;
}

// ---------------------------------------------------------------------------
// Kernel 2: combine partials -> mean_value, then the LAST of the 128 blocks
// (single atomic gate, one fence per block — cheap) runs top-6 + softmax.
// Top-6 = argmax iterate with smaller-index tie-break: same SET as
// lax.top_k; order irrelevant (softmax-weighted sum is permutation
// invariant). Fixed reduction orders -> deterministic; counter self-resets
// so the kernel is graph-replay safe. grid (B_, 4), 256 threads.
// ---------------------------------------------------------------------------
__global__ __launch_bounds__(256) void k_combine_topk() {
    __shared__ float sm[L_];
    __shared__ float wval[8];
    __shared__ int   widx[8];
    __shared__ int   s_idx[K_];
    __shared__ int   s_flag;

    const int b = blockIdx.x;
    const int q = blockIdx.y;          // 0..3
    const int t = threadIdx.x;

    // ---- combine: meanv[b, q*256 + t] ----
    {
        const int l = q * 256 + t;
        float s = 0.f;
#pragma unroll
        for (int g = 0; g < G_; ++g)
            s += g_partial[((size_t)b * G_ + g) * L_ + l];
        g_meanv[(size_t)b * L_ + l] = s * (1.0f / (float)HC_);
    }

    // ---- gate: last of 128 blocks proceeds ----
    __threadfence();
    if (t == 0) s_flag = (atomicAdd(&g_cnt, 1) == B_ * 4 - 1);
    __syncthreads();
    if (!s_flag) return;
    if (t == 0) g_cnt = 0;             // reset for graph replay
    __threadfence();                   // acquire: see all meanv writes

    const int wid = t >> 5;
    const int lid = t & 31;

    // batch-sum per column (ranking criterion; /B monotone)
#pragma unroll
    for (int j = 0; j < 4; ++j) {
        const int l = t + j * 256;
        float s = 0.f;
#pragma unroll 8
        for (int bb = 0; bb < B_; ++bb) s += g_meanv[(size_t)bb * L_ + l];
        sm[l] = s;
    }
    __syncthreads();

    for (int k = 0; k < K_; ++k) {
        float bv = -3.0e38f; int bi = 0x7fffffff;
#pragma unroll
        for (int j = 0; j < 4; ++j) {
            const int l = t + j * 256;
            const float v = sm[l];
            if (v > bv || (v == bv && l < bi)) { bv = v; bi = l; }
        }
#pragma unroll
        for (int off = 16; off > 0; off >>= 1) {
            float v2 = __shfl_down_sync(0xffffffffu, bv, off);
            int   i2 = __shfl_down_sync(0xffffffffu, bi, off);
            if (v2 > bv || (v2 == bv && i2 < bi)) { bv = v2; bi = i2; }
        }
        if (lid == 0) { wval[wid] = bv; widx[wid] = bi; }
        __syncthreads();
        if (t == 0) {
            float fv = wval[0]; int fi = widx[0];
#pragma unroll
            for (int w = 1; w < 8; ++w) {
                if (wval[w] > fv || (wval[w] == fv && widx[w] < fi)) {
                    fv = wval[w]; fi = widx[w];
                }
            }
            s_idx[k] = fi;
            g_idx[k] = fi;
            sm[fi]   = -3.0e38f;
        }
        __syncthreads();
    }

    // per-batch softmax over mean_value[b, idx[0..5]]
    if (t < B_) {
        const int bb = t;
        float w[K_];
        float m = -3.0e38f;
#pragma unroll
        for (int k = 0; k < K_; ++k) {
            w[k] = g_meanv[(size_t)bb * L_ + s_idx[k]];
            m = fmaxf(m, w[k]);
        }
        float sum = 0.f;
#pragma unroll
        for (int k = 0; k < K_; ++k) { w[k] = __expf(w[k] - m); sum += w[k]; }
        const float inv = 1.0f / sum;
#pragma unroll
        for (int k = 0; k < K_; ++k) g_wts[bb * K_ + k] = w[k] * inv;
    }
}

// ---------------------------------------------------------------------------
// Kernel 3: delays aggregation, NO shared memory.
// One block per row (16384 blocks, 256 threads, 4 outputs/thread). The six
// shifted streams are read straight from global: pass 1 fills L1D (4KB row,
// ~32KB working set/SM << 228KB), passes 2-6 hit L1. Per output the L1 pipe
// sees 6 LDG.32 + 1 STG.32 = 28B (vs 36B for the smem design), and there is
// no barrier, no STS, no staging serialization. All 24 gathers per thread
// are independent (MLP=24); lane-stride-1 addresses -> 1 wavefront each.
// ---------------------------------------------------------------------------
__global__ __launch_bounds__(256) void k_agg(const float* __restrict__ values,
                                             float* __restrict__ out) {
    const int row = blockIdx.x;             // 0 .. B*H*C-1
    const int t   = threadIdx.x;
    const int b   = row >> 9;               // row / (H_*C_)

    const float* __restrict__ v = values + (size_t)row * L_;
    float* __restrict__ o       = out    + (size_t)row * L_;

    float w0 = g_wts[b * K_ + 0], w1 = g_wts[b * K_ + 1], w2 = g_wts[b * K_ + 2];
    float w3 = g_wts[b * K_ + 3], w4 = g_wts[b * K_ + 4], w5 = g_wts[b * K_ + 5];
    int   i0 = g_idx[0], i1 = g_idx[1], i2 = g_idx[2];
    int   i3 = g_idx[3], i4 = g_idx[4], i5 = g_idx[5];

#pragma unroll
    for (int j = 0; j < 4; ++j) {
        const int l = t + j * 256;
        float acc;
        acc  = __ldg(&v[(l + i0) & (L_ - 1)]) * w0;
        acc += __ldg(&v[(l + i1) & (L_ - 1)]) * w1;
        acc += __ldg(&v[(l + i2) & (L_ - 1)]) * w2;
        acc += __ldg(&v[(l + i3) & (L_ - 1)]) * w3;
        acc += __ldg(&v[(l + i4) & (L_ - 1)]) * w4;
        acc += __ldg(&v[(l + i5) & (L_ - 1)]) * w5;
        o[l] = acc;
    }
}

// ---------------------------------------------------------------------------
extern "C" void kernel_launch(void* const* d_in, const int* in_sizes, int n_in,
                              void* d_out, int out_size) {
    const float* values = (const float*)d_in[0];
    const float* corr   = (const float*)d_in[1];
    float*       out    = (float*)d_out;

    dim3 g1(B_, G_);
    k_partial<<<g1, 256>>>(corr);
    dim3 g2(B_, 4);
    k_combine_topk<<<g2, 256>>>();
    k_agg<<<B_ * H_ * C_, 256>>>(values, out);
}